// round 5
// baseline (speedup 1.0000x reference)
#include <cuda_runtime.h>
#include <cstdint>

typedef unsigned long long ull;

#define DIM    64
#define CODES  512
#define NTOK   262144          // 64*64*64 tokens
#define TPB    512
#define TOKPB  512             // tokens per block (TM=1)
#define NBLK   (NTOK / TOKPB)  // 512
#define SROW   68              // floats per code row in smem (64 + pad), 272B
#define SROW_V2 17             // ulonglong2 per code row

// Output layout (float32, concatenated tuple):
// quantize_st[64^4], quant_loss[1], indices[64^3], commitment_loss[1],
// embedding_new[64*512], N_new[512], M_new[64*512]
#define OFF_Q    0L
#define OFF_QL   16777216L
#define OFF_IDX  16777217L
#define OFF_CL   17039361L
#define OFF_EMB  17039362L
#define OFF_N    17072130L
#define OFF_M    17072642L

#define SMEM_FLOATS (CODES*SROW + CODES + TOKPB)
#define SMEM_BYTES  (SMEM_FLOATS * 4)

// zero-by-invariant scratch: zero at module load; finalizing block re-zeros
// after consuming, so every kernel_launch (and every graph replay) starts clean.
__device__ float    g_ni[CODES];
__device__ float    g_eofxT[CODES * DIM];   // transposed: [code][dim]
__device__ float    g_loss;
__device__ unsigned g_count;

// ---- packed f32x2 helpers (ptxas won't auto-fuse; PTX only) ----
__device__ __forceinline__ ull fma2(ull a, ull b, ull c) {
    ull d; asm("fma.rn.f32x2 %0, %1, %2, %3;" : "=l"(d) : "l"(a), "l"(b), "l"(c)); return d;
}
__device__ __forceinline__ ull add2(ull a, ull b) {
    ull d; asm("add.rn.f32x2 %0, %1, %2;" : "=l"(d) : "l"(a), "l"(b)); return d;
}
__device__ __forceinline__ float sum2(ull a) {
    float lo, hi; asm("mov.b64 {%0,%1}, %2;" : "=f"(lo), "=f"(hi) : "l"(a)); return lo + hi;
}
__device__ __forceinline__ void unpack2(ull a, float& lo, float& hi) {
    asm("mov.b64 {%0,%1}, %2;" : "=f"(lo), "=f"(hi) : "l"(a));
}
__device__ __forceinline__ void red_v2(float* p, float a, float b) {
    asm volatile("red.global.add.v2.f32 [%0], {%1, %2};"
                 :: "l"(p), "f"(a), "f"(b) : "memory");
}

extern __shared__ float smem[];

__global__ void __launch_bounds__(TPB, 1)
vq_fused(const float* __restrict__ x, const float* __restrict__ emb,
         const float* __restrict__ Nin, const float* __restrict__ Min,
         float* __restrict__ out) {
    float* sE    = smem;                    // [CODES][SROW]
    float* sNorm = sE + CODES * SROW;       // [CODES]
    int*   sIdx  = (int*)(sNorm + CODES);   // [TOKPB]
    __shared__ unsigned sLast;

    const int tid = threadIdx.x;

    // load embedding transposed: sE[c][d] = emb[d*CODES + c]
    #pragma unroll
    for (int k = 0; k < (DIM * CODES) / TPB; k++) {
        int idx = k * TPB + tid;
        int d = idx >> 9, c = idx & (CODES - 1);
        sE[c * SROW + d] = emb[idx];
    }

    // x into registers while smem load settles
    const int token = blockIdx.x * TOKPB + tid;
    ull xp[32];  // 64 floats packed as f32x2
    {
        const ulonglong2* xg = (const ulonglong2*)(x + (size_t)token * DIM);
        #pragma unroll
        for (int j = 0; j < 16; j++) {
            ulonglong2 v = xg[j];
            xp[2 * j] = v.x; xp[2 * j + 1] = v.y;
        }
    }
    __syncthreads();

    // in-block code norms: thread c computes ||e_c||^2 (same scalar order as ref path)
    {
        const float* row = sE + tid * SROW;
        float s = 0.f;
        #pragma unroll
        for (int d = 0; d < DIM; d++) s = fmaf(row[d], row[d], s);
        sNorm[tid] = s;
    }
    __syncthreads();

    // argmin over codes of  ||e||^2 - 2 x.e   (||x||^2 constant per token)
    float best = 3.402823466e38f;
    int bestc = 0;
    const ulonglong2* ebase = (const ulonglong2*)sE;

    #pragma unroll 1
    for (int c = 0; c < CODES; c += 4) {
        const ulonglong2* e0 = ebase + (size_t)c * SROW_V2;
        const ulonglong2* e1 = e0 + SROW_V2;
        const ulonglong2* e2 = e1 + SROW_V2;
        const ulonglong2* e3 = e2 + SROW_V2;
        ull a0 = 0, b0 = 0, a1 = 0, b1 = 0, a2 = 0, b2 = 0, a3 = 0, b3 = 0;
        #pragma unroll
        for (int j = 0; j < 16; j++) {
            ull xl = xp[2 * j], xh = xp[2 * j + 1];
            ulonglong2 v0 = e0[j], v1 = e1[j], v2 = e2[j], v3 = e3[j];
            a0 = fma2(xl, v0.x, a0); b0 = fma2(xh, v0.y, b0);
            a1 = fma2(xl, v1.x, a1); b1 = fma2(xh, v1.y, b1);
            a2 = fma2(xl, v2.x, a2); b2 = fma2(xh, v2.y, b2);
            a3 = fma2(xl, v3.x, a3); b3 = fma2(xh, v3.y, b3);
        }
        float d0 = fmaf(-2.f, sum2(add2(a0, b0)), sNorm[c]);
        float d1 = fmaf(-2.f, sum2(add2(a1, b1)), sNorm[c + 1]);
        float d2 = fmaf(-2.f, sum2(add2(a2, b2)), sNorm[c + 2]);
        float d3 = fmaf(-2.f, sum2(add2(a3, b3)), sNorm[c + 3]);
        if (d0 < best) { best = d0; bestc = c; }
        if (d1 < best) { best = d1; bestc = c + 1; }
        if (d2 < best) { best = d2; bestc = c + 2; }
        if (d3 < best) { best = d3; bestc = c + 3; }
    }

    sIdx[tid] = bestc;
    out[OFF_IDX + token] = (float)bestc;
    atomicAdd(&g_ni[bestc], 1.0f);

    // loss partial + eofx segment-sum scatter (transposed layout, red.v2)
    float lsum = 0.f;
    {
        const float* eb = sE + bestc * SROW;
        float* gb = g_eofxT + bestc * DIM;
        #pragma unroll
        for (int j = 0; j < 32; j++) {
            float x0, x1; unpack2(xp[j], x0, x1);
            float t0 = x0 - eb[2 * j], t1 = x1 - eb[2 * j + 1];
            lsum = fmaf(t0, t0, lsum);
            lsum = fmaf(t1, t1, lsum);
            red_v2(gb + 2 * j, x0, x1);
        }
    }
    #pragma unroll
    for (int o = 16; o > 0; o >>= 1)
        lsum += __shfl_xor_sync(0xffffffffu, lsum, o);
    if ((tid & 31) == 0) atomicAdd(&g_loss, lsum);

    // coalesced vectorized quantize_st write (q == quantize numerically)
    __syncthreads();
    float4* out4 = (float4*)(out + OFF_Q) + (size_t)blockIdx.x * (TOKPB * DIM / 4);
    #pragma unroll 1
    for (int it = 0; it < (TOKPB * DIM / 4) / TPB; it++) {   // 16 iters
        int idx4 = it * TPB + tid;
        int t = idx4 >> 4, dq = idx4 & 15;
        out4[idx4] = ((const float4*)(sE + sIdx[t] * SROW))[dq];
    }

    // ---- last-block finalize: EMA update + smoothing + losses + re-zero ----
    __syncthreads();
    if (tid == 0) {
        __threadfence();
        unsigned r = atomicAdd(&g_count, 1u);
        sLast = (r == NBLK - 1) ? 1u : 0u;
    }
    __syncthreads();
    if (sLast) {
        __threadfence();
        const float DEC = 0.99f, OMD = 1.0f - 0.99f;
        const int c = tid;   // one thread per code

        float Nn = fmaf(Nin[c], DEC, OMD * __ldcg(&g_ni[c]));
        out[OFF_N + c] = Nn;
        g_ni[c] = 0.f;

        sNorm[c] = Nn;
        __syncthreads();
        for (int s = CODES / 2; s > 0; s >>= 1) {
            if (c < s) sNorm[c] += sNorm[c + s];
            __syncthreads();
        }
        float n = sNorm[0];
        float Ns = (Nn + 1e-5f) / (n + CODES * 1e-5f) * n;

        #pragma unroll
        for (int d = 0; d < DIM; d++) {
            int i = d * CODES + c;
            float Mn = fmaf(Min[i], DEC, OMD * __ldcg(&g_eofxT[c * DIM + d]));
            out[OFF_M + i] = Mn;
            out[OFF_EMB + i] = Mn / Ns;
            g_eofxT[c * DIM + d] = 0.f;
        }
        if (c == 0) {
            float l = __ldcg(&g_loss) * (1.0f / 16777216.0f);
            out[OFF_QL] = l;   // quant_loss
            out[OFF_CL] = l;   // commitment_loss (numerically identical)
            g_loss = 0.f;
            g_count = 0u;
        }
    }
}

extern "C" void kernel_launch(void* const* d_in, const int* in_sizes, int n_in,
                              void* d_out, int out_size) {
    const float* x   = (const float*)d_in[0];
    const float* emb = (const float*)d_in[1];
    const float* N   = (const float*)d_in[2];
    const float* M   = (const float*)d_in[3];
    float* out = (float*)d_out;

    cudaFuncSetAttribute(vq_fused, cudaFuncAttributeMaxDynamicSharedMemorySize,
                         SMEM_BYTES);
    vq_fused<<<NBLK, TPB, SMEM_BYTES>>>(x, emb, N, M, out);
}

// round 6
// speedup vs baseline: 1.4471x; 1.4471x over previous
#include <cuda_runtime.h>
#include <cstdint>

typedef unsigned long long ull;

#define DIM    64
#define CODES  512
#define NTOK   262144
#define TPB    256
#define BLK_TOK 512
#define NBLK   (NTOK / BLK_TOK)   // 512
#define PASSES 8
#define TOKP   64                 // tokens per pass
#define PITCHE 516                // e tile pitch (floats)
#define PITCHX 68                 // x tile pitch (floats)

// smem offsets (floats)
#define SM_E     0
#define SM_X     (64 * PITCHE)            // 33024
#define SM_NORM  (SM_X + 64 * PITCHX)     // 37376
#define SM_RBEST (SM_NORM + 512)          // 37888
#define SM_RIDX  (SM_RBEST + 256)         // 38144
#define SM_IDX   (SM_RIDX + 256)          // 38400
#define SM_FLOATS (SM_IDX + 64)           // 38464
#define SMEM_BYTES (SM_FLOATS * 4)        // 153856

// Output layout (float32, concatenated tuple)
#define OFF_Q    0L
#define OFF_QL   16777216L
#define OFF_IDX  16777217L
#define OFF_CL   17039361L
#define OFF_EMB  17039362L
#define OFF_N    17072130L
#define OFF_M    17072642L

// zero-by-invariant scratch (finalizing block re-zeros after consuming)
__device__ float    g_ni[CODES];
__device__ float    g_eofxT[CODES * DIM];   // [code][dim]
__device__ float    g_loss;
__device__ unsigned g_count;

__device__ __forceinline__ ull fma2(ull a, ull b, ull c) {
    ull d; asm("fma.rn.f32x2 %0, %1, %2, %3;" : "=l"(d) : "l"(a), "l"(b), "l"(c)); return d;
}
__device__ __forceinline__ ull dup2(float v) {
    ull d; asm("mov.b64 %0, {%1, %1};" : "=l"(d) : "f"(v)); return d;
}
__device__ __forceinline__ void unpack2(ull a, float& lo, float& hi) {
    asm("mov.b64 {%0,%1}, %2;" : "=f"(lo), "=f"(hi) : "l"(a));
}
__device__ __forceinline__ void red_v2(float* p, float a, float b) {
    asm volatile("red.global.add.v2.f32 [%0], {%1, %2};"
                 :: "l"(p), "f"(a), "f"(b) : "memory");
}

extern __shared__ float smem[];

__global__ void __launch_bounds__(TPB, 1)
vq_fused(const float* __restrict__ x, const float* __restrict__ emb,
         const float* __restrict__ Nin, const float* __restrict__ Min,
         float* __restrict__ out) {
    float* sE    = smem + SM_E;      // [64][PITCHE] e, native [dim][code]
    float* sX    = smem + SM_X;      // [64][PITCHX] x transposed [dim][token]
    float* sNorm = smem + SM_NORM;   // [512]
    float* sRb   = smem + SM_RBEST;  // [64][4]
    int*   sRi   = (int*)(smem + SM_RIDX);
    int*   sIdx  = (int*)(smem + SM_IDX);
    __shared__ unsigned sLast;

    const int tid  = threadIdx.x;
    const int lane = tid & 31, wid = tid >> 5;
    const int wt = wid >> 2, wc = wid & 3;   // token-group / code-slice
    const int tl = lane >> 4, cl = lane & 15;
    const int tbase = wt * 32 + tl * 16;     // local token base (0..48)
    const int cbase = wc * 128 + cl * 8;     // code base

    // load embedding [d][c] into sE (pitched), vectorized
    {
        const float4* e4 = (const float4*)emb;
        #pragma unroll
        for (int it = 0; it < 32; it++) {
            int idx = it * TPB + tid;
            int d = idx >> 7, c4 = idx & 127;
            *(float4*)(sE + d * PITCHE + c4 * 4) = e4[idx];
        }
    }
    __syncthreads();

    // code norms (column sums, conflict-free lanes)
    #pragma unroll
    for (int h = 0; h < 2; h++) {
        int c = h * TPB + tid;
        float s = 0.f;
        #pragma unroll
        for (int k = 0; k < 64; k++) {
            float v = sE[k * PITCHE + c];
            s = fmaf(v, v, s);
        }
        sNorm[c] = s;
    }
    __syncthreads();

    float nrm[8];
    #pragma unroll
    for (int c = 0; c < 8; c++) nrm[c] = sNorm[cbase + c];

    for (int pass = 0; pass < PASSES; pass++) {
        const int tok0 = blockIdx.x * BLK_TOK + pass * TOKP;
        __syncthreads();   // protect sX / sIdx / sRb reuse
        // x tile: 64 tokens x 64 dims, transposed into sX[d][t]
        {
            const float4* xg = (const float4*)(x + (size_t)tok0 * DIM);
            #pragma unroll
            for (int it = 0; it < 4; it++) {
                int idx = it * TPB + tid;        // 0..1023
                int t = idx >> 4, d4 = idx & 15;
                float4 v = xg[t * 16 + d4];
                sX[(d4 * 4 + 0) * PITCHX + t] = v.x;
                sX[(d4 * 4 + 1) * PITCHX + t] = v.y;
                sX[(d4 * 4 + 2) * PITCHX + t] = v.z;
                sX[(d4 * 4 + 3) * PITCHX + t] = v.w;
            }
        }
        __syncthreads();

        // K-loop: 16 tokens x 8 codes per thread, f32x2 packed over token pairs
        ull acc[8][8];
        #pragma unroll
        for (int c = 0; c < 8; c++)
            #pragma unroll
            for (int j = 0; j < 8; j++) acc[c][j] = 0ull;

        const float* ep = sE + cbase;
        const float* xp = sX + tbase;
        #pragma unroll 4
        for (int k = 0; k < 64; k++) {
            float4 e0 = *(const float4*)ep;
            float4 e1 = *(const float4*)(ep + 4);
            ulonglong2 x0 = *(const ulonglong2*)xp;
            ulonglong2 x1 = *(const ulonglong2*)(xp + 4);
            ulonglong2 x2 = *(const ulonglong2*)(xp + 8);
            ulonglong2 x3 = *(const ulonglong2*)(xp + 12);
            ull xs[8] = {x0.x, x0.y, x1.x, x1.y, x2.x, x2.y, x3.x, x3.y};
            float ec[8] = {e0.x, e0.y, e0.z, e0.w, e1.x, e1.y, e1.z, e1.w};
            #pragma unroll
            for (int c = 0; c < 8; c++) {
                ull ed = dup2(ec[c]);
                #pragma unroll
                for (int j = 0; j < 8; j++)
                    acc[c][j] = fma2(xs[j], ed, acc[c][j]);
            }
            ep += PITCHE; xp += PITCHX;
        }

        // distances + thread-local argmin (ascending code, first-min ties)
        float best[16]; int bidx[16];
        #pragma unroll
        for (int tt = 0; tt < 16; tt++) { best[tt] = 3.402823466e38f; bidx[tt] = 0; }
        #pragma unroll
        for (int c = 0; c < 8; c++) {
            float nr = nrm[c]; int cc = cbase + c;
            #pragma unroll
            for (int j = 0; j < 8; j++) {
                float lo, hi; unpack2(acc[c][j], lo, hi);
                float dl = fmaf(-2.f, lo, nr);
                float dh = fmaf(-2.f, hi, nr);
                if (dl < best[2 * j])     { best[2 * j] = dl;     bidx[2 * j] = cc; }
                if (dh < best[2 * j + 1]) { best[2 * j + 1] = dh; bidx[2 * j + 1] = cc; }
            }
        }
        // reduce across 16 code-lanes (same tl); min-index tie-break
        #pragma unroll
        for (int off = 8; off; off >>= 1) {
            #pragma unroll
            for (int tt = 0; tt < 16; tt++) {
                float ob = __shfl_xor_sync(0xffffffffu, best[tt], off);
                int   oc = __shfl_xor_sync(0xffffffffu, bidx[tt], off);
                if (ob < best[tt] || (ob == best[tt] && oc < bidx[tt])) {
                    best[tt] = ob; bidx[tt] = oc;
                }
            }
        }
        if (cl == 0) {
            #pragma unroll
            for (int tt = 0; tt < 16; tt++) {
                sRb[(tbase + tt) * 4 + wc] = best[tt];
                sRi[(tbase + tt) * 4 + wc] = bidx[tt];
            }
        }
        __syncthreads();

        // final argmin across 4 slices + per-token tail
        if (tid < TOKP) {
            const int t = tid;
            float b = sRb[t * 4]; int bc = sRi[t * 4];
            #pragma unroll
            for (int s = 1; s < 4; s++) {
                float ob = sRb[t * 4 + s]; int oc = sRi[t * 4 + s];
                if (ob < b || (ob == b && oc < bc)) { b = ob; bc = oc; }
            }
            sIdx[t] = bc;
            out[OFF_IDX + tok0 + t] = (float)bc;
            atomicAdd(&g_ni[bc], 1.0f);

            float lsum = 0.f;
            float* gb = g_eofxT + bc * DIM;
            #pragma unroll
            for (int d = 0; d < 64; d += 2) {
                float x0 = sX[d * PITCHX + t];
                float x1 = sX[(d + 1) * PITCHX + t];
                float q0 = sE[d * PITCHE + bc];
                float q1 = sE[(d + 1) * PITCHE + bc];
                float t0 = x0 - q0, t1 = x1 - q1;
                lsum = fmaf(t0, t0, lsum);
                lsum = fmaf(t1, t1, lsum);
                red_v2(gb + d, x0, x1);
            }
            #pragma unroll
            for (int o = 16; o; o >>= 1)
                lsum += __shfl_xor_sync(0xffffffffu, lsum, o);
            if ((tid & 31) == 0) atomicAdd(&g_loss, lsum);
        }
        __syncthreads();

        // quantize_st writeback: thread = (token, quarter of dims)
        {
            int t = tid >> 2, q = tid & 3;
            int c = sIdx[t];
            float* ob = out + OFF_Q + (size_t)(tok0 + t) * DIM + q * 16;
            #pragma unroll
            for (int i4 = 0; i4 < 4; i4++) {
                float4 v;
                v.x = sE[(q * 16 + i4 * 4 + 0) * PITCHE + c];
                v.y = sE[(q * 16 + i4 * 4 + 1) * PITCHE + c];
                v.z = sE[(q * 16 + i4 * 4 + 2) * PITCHE + c];
                v.w = sE[(q * 16 + i4 * 4 + 3) * PITCHE + c];
                *(float4*)(ob + i4 * 4) = v;
            }
        }
    }

    // ---- last-block finalize: EMA + smoothing + losses + re-zero ----
    __syncthreads();
    if (tid == 0) {
        __threadfence();
        unsigned r = atomicAdd(&g_count, 1u);
        sLast = (r == NBLK - 1) ? 1u : 0u;
    }
    __syncthreads();
    if (sLast) {
        __threadfence();
        const float DEC = 0.99f, OMD = 1.0f - 0.99f;
        float Nn[2];
        #pragma unroll
        for (int h = 0; h < 2; h++) {
            int c = h * TPB + tid;
            Nn[h] = fmaf(Nin[c], DEC, OMD * __ldcg(&g_ni[c]));
            out[OFF_N + c] = Nn[h];
            g_ni[c] = 0.f;
        }
        sNorm[tid] = Nn[0] + Nn[1];
        __syncthreads();
        for (int s = TPB / 2; s > 0; s >>= 1) {
            if (tid < s) sNorm[tid] += sNorm[tid + s];
            __syncthreads();
        }
        float n = sNorm[0];
        #pragma unroll
        for (int h = 0; h < 2; h++) {
            int c = h * TPB + tid;
            float Ns = (Nn[h] + 1e-5f) / (n + CODES * 1e-5f) * n;
            #pragma unroll
            for (int d = 0; d < DIM; d++) {
                int i = d * CODES + c;
                float Mn = fmaf(Min[i], DEC, OMD * __ldcg(&g_eofxT[c * DIM + d]));
                out[OFF_M + i] = Mn;
                out[OFF_EMB + i] = Mn / Ns;
                g_eofxT[c * DIM + d] = 0.f;
            }
        }
        if (tid == 0) {
            float l = __ldcg(&g_loss) * (1.0f / 16777216.0f);
            out[OFF_QL] = l;
            out[OFF_CL] = l;
            g_loss = 0.f;
            g_count = 0u;
        }
    }
}

extern "C" void kernel_launch(void* const* d_in, const int* in_sizes, int n_in,
                              void* d_out, int out_size) {
    const float* x   = (const float*)d_in[0];
    const float* emb = (const float*)d_in[1];
    const float* N   = (const float*)d_in[2];
    const float* M   = (const float*)d_in[3];
    float* out = (float*)d_out;

    cudaFuncSetAttribute(vq_fused, cudaFuncAttributeMaxDynamicSharedMemorySize,
                         SMEM_BYTES);
    vq_fused<<<NBLK, TPB, SMEM_BYTES>>>(x, emb, N, M, out);
}

// round 8
// speedup vs baseline: 1.9371x; 1.3386x over previous
#include <cuda_runtime.h>
#include <cstdint>

#define DIM    64
#define CODES  512
#define NTOK   262144
#define TPB    256
#define NBLK   2048            // NTOK / 128 tokens per block

// Output layout (float32, concatenated tuple)
#define OFF_Q    0L
#define OFF_QL   16777216L
#define OFF_IDX  16777217L
#define OFF_CL   17039361L
#define OFF_EMB  17039362L
#define OFF_N    17072130L
#define OFF_M    17072642L

// smem float offsets for vq_mma
#define SA_F     0          // A permuted: 16384 floats (64KB)
#define SB_F     16384      // B double buffer: 2 x 16384 floats
#define SN_F     49152      // norms: 512
#define SXN_F    49664      // xnorm: 128
#define SRB_F    49792      // per-(token,cg) best: 256
#define SRI_F    50048      // per-(token,cg) idx: 256
#define SM_FLOATS 50304
#define SMEM_BYTES (SM_FLOATS * 4)   // 201216

__device__ float  g_embT[CODES * DIM];   // [c][d] fp32 for gather
__device__ float2 g_bperm[32768];        // pre-permuted tf32-split B fragments
__device__ float  g_norm[CODES];
__device__ float  g_ni[CODES];
__device__ float  g_eofxT[CODES * DIM];  // [c][d]
__device__ float  g_loss;
__device__ int    g_idx[NTOK];
__device__ float  g_Ns[CODES];

// ---------------- helpers ----------------
__device__ __forceinline__ float tf32_rnd(float v) {
    uint32_t u; asm("cvt.rna.tf32.f32 %0, %1;" : "=r"(u) : "f"(v));
    return __uint_as_float(u);
}
__device__ __forceinline__ void red_f(float* p, float v) {
    asm volatile("red.global.add.f32 [%0], %1;" :: "l"(p), "f"(v) : "memory");
}
__device__ __forceinline__ void red_v2(float* p, float a, float b) {
    asm volatile("red.global.add.v2.f32 [%0], {%1, %2};" :: "l"(p), "f"(a), "f"(b) : "memory");
}
__device__ __forceinline__ void mma_tf32(float* d, const uint4 a, const uint2 b) {
    asm("mma.sync.aligned.m16n8k8.row.col.f32.tf32.tf32.f32 "
        "{%0,%1,%2,%3}, {%4,%5,%6,%7}, {%8,%9}, {%0,%1,%2,%3};"
        : "+f"(d[0]), "+f"(d[1]), "+f"(d[2]), "+f"(d[3])
        : "r"(a.x), "r"(a.y), "r"(a.z), "r"(a.w), "r"(b.x), "r"(b.y));
}
__device__ __forceinline__ uint32_t smem_u32(const void* p) {
    uint32_t a;
    asm("{ .reg .u64 t; cvta.to.shared.u64 t, %1; cvt.u32.u64 %0, t; }" : "=r"(a) : "l"(p));
    return a;
}
__device__ __forceinline__ void cp16(uint32_t dst, const void* src) {
    asm volatile("cp.async.cg.shared.global [%0], [%1], 16;" :: "r"(dst), "l"(src) : "memory");
}
#define CP_COMMIT() asm volatile("cp.async.commit_group;" ::: "memory")

// ---------------- k1a: zero scratch ----------------
__global__ void vq_zero() {
    int idx = blockIdx.x * 512 + threadIdx.x;
    g_eofxT[idx] = 0.f;
    if (idx < CODES) g_ni[idx] = 0.f;
    if (idx == 0) g_loss = 0.f;
}

// ---------------- k1b: norms + transpose + tf32-split permuted B ----------------
__global__ void vq_split(const float* __restrict__ emb) {
    const int idx = blockIdx.x * 512 + threadIdx.x;   // 0..32767

    // transposed fp32 copy for gather
    { int c = idx >> 6, d = idx & 63; g_embT[idx] = emb[d * CODES + c]; }

    // exact code norms
    if (idx < CODES) {
        float s = 0.f;
        #pragma unroll
        for (int d = 0; d < DIM; d++) {
            float v = emb[d * CODES + idx];
            s = fmaf(v, v, s);
        }
        g_norm[idx] = s;
    }

    // permuted tf32-split B fragment slots:
    // s = ((((p*2+cg)*8+nf)*8+ks)*2+t)*32 + l
    {
        int l  = idx & 31;
        int t  = (idx >> 5) & 1;
        int ks = (idx >> 6) & 7;
        int nf = (idx >> 9) & 7;
        int cg = (idx >> 12) & 1;
        int p  = idx >> 13;
        int code = p * 128 + cg * 64 + nf * 8 + (l >> 2);
        int k0 = ks * 8 + (l & 3);
        float v0 = emb[k0 * CODES + code];
        float v1 = emb[(k0 + 4) * CODES + code];
        float h0 = tf32_rnd(v0), h1 = tf32_rnd(v1);
        float2 o;
        if (t == 0) { o.x = h0; o.y = h1; }
        else        { o.x = tf32_rnd(v0 - h0); o.y = tf32_rnd(v1 - h1); }
        g_bperm[idx] = o;
    }
}

// ---------------- k2: tensor-core assign (mma.sync tf32, 4-term split) ----------------
extern __shared__ float sm[];

__global__ void __launch_bounds__(TPB, 1)
vq_mma(const float* __restrict__ x, float* __restrict__ out) {
    const int tid  = threadIdx.x;
    const int lane = tid & 31, wid = tid >> 5;
    const int tg = wid & 3;          // token group (32 tokens)
    const int cg = wid >> 2;         // code group (64 codes per phase)
    const int g  = lane >> 2;        // groupID
    const int tig = lane & 3;        // thread in group

    float* sA  = sm + SA_F;
    float* sN  = sm + SN_F;
    float* sXn = sm + SXN_F;
    float* sRb = sm + SRB_F;
    int*   sRi = (int*)(sm + SRI_F);
    const uint32_t smbase = smem_u32(sm);

    // norms to smem
    #pragma unroll
    for (int h = 0; h < 2; h++) sN[h * TPB + tid] = g_norm[h * TPB + tid];

    // ---- load x: thread owns (token = tid/2, half = tid&1) -> 32 floats ----
    const int tok  = tid >> 1;
    const int half = tid & 1;
    const int gtok0 = blockIdx.x * 128;
    float xv[32];
    {
        const float4* xg = (const float4*)(x + (size_t)(gtok0 + tok) * DIM + half * 32);
        #pragma unroll
        for (int j = 0; j < 8; j++) {
            float4 v = xg[j];
            xv[4*j] = v.x; xv[4*j+1] = v.y; xv[4*j+2] = v.z; xv[4*j+3] = v.w;
        }
    }
    // xnorm (pair-combined)
    {
        float xn = 0.f;
        #pragma unroll
        for (int j = 0; j < 32; j++) xn = fmaf(xv[j], xv[j], xn);
        xn += __shfl_xor_sync(0xffffffffu, xn, 1);
        if (half == 0) sXn[tok] = xn;
    }
    // ---- write A permuted (tf32 split h/l) ----
    {
        const int ttg = tok >> 5, tmf = (tok >> 4) & 1, r = tok & 15;
        const int abase = (ttg * 2 + tmf) * 8;           // *8 ksteps
        #pragma unroll
        for (int j = 0; j < 32; j++) {
            int k = half * 32 + j;
            int ks = k >> 3, kk = k & 7;
            int al = (r & 7) * 4 + (kk & 3);
            int ar = (r >> 3) | (((kk >> 2) & 1) << 1);
            float v = xv[j];
            float hf = tf32_rnd(v);
            float lf = tf32_rnd(v - hf);
            int base = ((abase + ks) * 2) * 128 + al * 4 + ar;
            sA[base] = hf;            // term 0
            sA[base + 128] = lf;      // term 1
        }
    }

    // ---- prologue: cp.async B phase 0 ----
    {
        const char* src = (const char*)g_bperm;
        #pragma unroll
        for (int i = 0; i < 16; i++) {
            int off = (i * TPB + tid) * 16;
            cp16(smbase + (SB_F * 4) + off, src + off);
        }
        CP_COMMIT();
    }

    float best[4];  int bidx[4];
    #pragma unroll
    for (int s = 0; s < 4; s++) { best[s] = 3.402823466e38f; bidx[s] = 0; }

    for (int p = 0; p < 4; p++) {
        if (p < 3) {   // prefetch next phase into other buffer
            const char* src = (const char*)g_bperm + (p + 1) * 65536;
            uint32_t dst = smbase + (SB_F + ((p + 1) & 1) * 16384) * 4;
            #pragma unroll
            for (int i = 0; i < 16; i++) {
                int off = (i * TPB + tid) * 16;
                cp16(dst + off, src + off);
            }
            CP_COMMIT();
            asm volatile("cp.async.wait_group 1;" ::: "memory");
        } else {
            asm volatile("cp.async.wait_group 0;" ::: "memory");
        }
        __syncthreads();

        const float* bb = sm + SB_F + (p & 1) * 16384;
        float acc[2][8][4];
        #pragma unroll
        for (int mf = 0; mf < 2; mf++)
            #pragma unroll
            for (int nf = 0; nf < 8; nf++)
                #pragma unroll
                for (int q = 0; q < 4; q++) acc[mf][nf][q] = 0.f;

        #pragma unroll
        for (int ks = 0; ks < 8; ks++) {
            uint4 afr[2][2];
            #pragma unroll
            for (int mf = 0; mf < 2; mf++)
                #pragma unroll
                for (int t = 0; t < 2; t++)
                    afr[mf][t] = *(const uint4*)&sA[(((tg * 2 + mf) * 8 + ks) * 2 + t) * 128 + lane * 4];
            uint2 bfr[8][2];
            #pragma unroll
            for (int nf = 0; nf < 8; nf++)
                #pragma unroll
                for (int t = 0; t < 2; t++)
                    bfr[nf][t] = *(const uint2*)&bb[((((cg * 8 + nf) * 8 + ks) * 2 + t) * 32 + lane) * 2];
            #pragma unroll
            for (int xt = 0; xt < 2; xt++)
                #pragma unroll
                for (int et = 0; et < 2; et++)
                    #pragma unroll
                    for (int mf = 0; mf < 2; mf++)
                        #pragma unroll
                        for (int nf = 0; nf < 8; nf++)
                            mma_tf32(acc[mf][nf], afr[mf][xt], bfr[nf][et]);
        }

        // epilogue: dist + running argmin (codes ascending)
        #pragma unroll
        for (int nf = 0; nf < 8; nf++) {
            int c0 = p * 128 + cg * 64 + nf * 8 + 2 * tig;
            float n0 = sN[c0], n1 = sN[c0 + 1];
            #pragma unroll
            for (int mf = 0; mf < 2; mf++) {
                float d00 = fmaf(-2.f, acc[mf][nf][0], n0);
                float d01 = fmaf(-2.f, acc[mf][nf][1], n1);
                float d10 = fmaf(-2.f, acc[mf][nf][2], n0);
                float d11 = fmaf(-2.f, acc[mf][nf][3], n1);
                int s0 = mf * 2, s1 = mf * 2 + 1;
                if (d00 < best[s0]) { best[s0] = d00; bidx[s0] = c0; }
                if (d01 < best[s0]) { best[s0] = d01; bidx[s0] = c0 + 1; }
                if (d10 < best[s1]) { best[s1] = d10; bidx[s1] = c0; }
                if (d11 < best[s1]) { best[s1] = d11; bidx[s1] = c0 + 1; }
            }
        }
        __syncthreads();
    }

    // reduce across tig lanes (same tokens), tie -> min index
    #pragma unroll
    for (int off = 1; off <= 2; off <<= 1) {
        #pragma unroll
        for (int s = 0; s < 4; s++) {
            float ob = __shfl_xor_sync(0xffffffffu, best[s], off);
            int   oc = __shfl_xor_sync(0xffffffffu, bidx[s], off);
            if (ob < best[s] || (ob == best[s] && oc < bidx[s])) { best[s] = ob; bidx[s] = oc; }
        }
    }
    if (tig == 0) {
        #pragma unroll
        for (int s = 0; s < 4; s++) {
            int t = tg * 32 + g + s * 8;
            sRb[t * 2 + cg] = best[s];
            sRi[t * 2 + cg] = bidx[s];
        }
    }
    __syncthreads();

    // combine code-groups + per-token outputs
    if (tid < 128) {
        float b0 = sRb[tid * 2];     int i0 = sRi[tid * 2];
        float b1 = sRb[tid * 2 + 1]; int i1 = sRi[tid * 2 + 1];
        int bc; float bd;
        if (b1 < b0 || (b1 == b0 && i1 < i0)) { bc = i1; bd = b1; } else { bc = i0; bd = b0; }
        int gt = gtok0 + tid;
        g_idx[gt] = bc;
        out[OFF_IDX + gt] = (float)bc;
        red_f(&g_ni[bc], 1.0f);
        sRi[tid * 2] = bc;
        float l = bd + sXn[tid];
        #pragma unroll
        for (int o = 16; o; o >>= 1) l += __shfl_xor_sync(0xffffffffu, l, o);
        if ((tid & 31) == 0) red_f(&g_loss, l);
    }
    __syncthreads();

    // eofx scatter from x registers (thread's 32 dims)
    {
        int bc = sRi[tok * 2];
        float* gb = g_eofxT + bc * DIM + half * 32;
        #pragma unroll
        for (int j = 0; j < 16; j++) red_v2(gb + 2 * j, xv[2 * j], xv[2 * j + 1]);
    }
}

// ---------------- k3: quantize gather (warp per token group) ----------------
__global__ void __launch_bounds__(256)
vq_gather(float* __restrict__ out) {
    extern __shared__ float sE[];   // [512][64]
    const int tid = threadIdx.x;
    {
        const float4* src = (const float4*)g_embT;
        float4* dst = (float4*)sE;
        #pragma unroll
        for (int it = 0; it < 32; it++) dst[it * 256 + tid] = src[it * 256 + tid];
    }
    __syncthreads();
    const int warp = tid >> 5, lane = tid & 31;
    const int tbase = blockIdx.x * 1024 + warp * 128;
    int my[4];
    #pragma unroll
    for (int i = 0; i < 4; i++) my[i] = g_idx[tbase + i * 32 + lane];
    #pragma unroll
    for (int i = 0; i < 4; i++) {
        #pragma unroll 8
        for (int s = 0; s < 32; s++) {
            int c = __shfl_sync(0xffffffffu, my[i], s);
            float2 q = *(const float2*)&sE[c * DIM + lane * 2];
            *(float2*)&out[OFF_Q + (size_t)(tbase + i * 32 + s) * DIM + lane * 2] = q;
        }
    }
}

// ---------------- k4a: N_new, smoothing denom, losses ----------------
__global__ void vq_n(const float* __restrict__ Nin, float* __restrict__ out) {
    __shared__ float red[CODES];
    const int c = threadIdx.x;
    const float OMD = 1.0f - 0.99f;
    float Nn = fmaf(Nin[c], 0.99f, OMD * g_ni[c]);
    out[OFF_N + c] = Nn;
    red[c] = Nn;
    __syncthreads();
    for (int s = CODES / 2; s > 0; s >>= 1) {
        if (c < s) red[c] += red[c + s];
        __syncthreads();
    }
    float n = red[0];
    g_Ns[c] = (Nn + 1e-5f) / (n + CODES * 1e-5f) * n;
    if (c == 0) {
        float l = g_loss * (1.0f / 16777216.0f);
        out[OFF_QL] = l;
        out[OFF_CL] = l;
    }
}

// ---------------- k4b: M_new + embedding_new ----------------
__global__ void vq_m(const float* __restrict__ Min, float* __restrict__ out) {
    const int idx = blockIdx.x * 512 + threadIdx.x;   // 32768
    const int d = idx >> 9, c = idx & (CODES - 1);
    const float OMD = 1.0f - 0.99f;
    float Mn = fmaf(Min[idx], 0.99f, OMD * g_eofxT[c * DIM + d]);
    out[OFF_M + idx] = Mn;
    out[OFF_EMB + idx] = Mn / g_Ns[c];
}

extern "C" void kernel_launch(void* const* d_in, const int* in_sizes, int n_in,
                              void* d_out, int out_size) {
    const float* x   = (const float*)d_in[0];
    const float* emb = (const float*)d_in[1];
    const float* N   = (const float*)d_in[2];
    const float* M   = (const float*)d_in[3];
    float* out = (float*)d_out;

    cudaFuncSetAttribute(vq_mma, cudaFuncAttributeMaxDynamicSharedMemorySize, SMEM_BYTES);
    cudaFuncSetAttribute(vq_gather, cudaFuncAttributeMaxDynamicSharedMemorySize, 131072);

    vq_zero<<<64, 512>>>();
    vq_split<<<64, 512>>>(emb);
    vq_mma<<<NBLK, TPB, SMEM_BYTES>>>(x, out);
    vq_gather<<<256, 256, 131072>>>(out);
    vq_n<<<1, CODES>>>(N, out);
    vq_m<<<64, 512>>>(M, out);
}